// round 2
// baseline (speedup 1.0000x reference)
#include <cuda_runtime.h>
#include <cstdint>

#define Bb 2
#define Ss 2048
#define Dd 4096
#define Hh 32
#define HKVn 8
#define HDd 128
#define Mm (Bb*Ss)

// Scratch (device globals: allocation-free)
__device__ float g_q[(size_t)Mm * Dd];
__device__ float g_k[(size_t)Mm * HKVn * HDd];
__device__ float g_v[(size_t)Mm * HKVn * HDd];
__device__ float g_ctx[(size_t)Mm * Dd];

__device__ __forceinline__ float f2tf(float x) {
    unsigned r;
    asm("cvt.rna.tf32.f32 %0, %1;" : "=r"(r) : "f"(x));
    return __uint_as_float(r);
}

__device__ __forceinline__ void mma_tf32(float* c, const unsigned* a, const unsigned* b) {
    asm volatile(
        "mma.sync.aligned.m16n8k8.row.col.f32.tf32.tf32.f32 "
        "{%0,%1,%2,%3}, {%4,%5,%6,%7}, {%8,%9}, {%0,%1,%2,%3};"
        : "+f"(c[0]), "+f"(c[1]), "+f"(c[2]), "+f"(c[3])
        : "r"(a[0]), "r"(a[1]), "r"(a[2]), "r"(a[3]), "r"(b[0]), "r"(b[1]));
}

// ---------------------------------------------------------------------------
// Tiled tf32 GEMM: C[M,N] = A[M,K] @ B[K,N], all row-major fp32.
// Block tile 128x128, BK=32, 256 threads = 8 warps (2 M x 4 N), warp tile 64x32.
// ---------------------------------------------------------------------------
__global__ __launch_bounds__(256, 2) void gemm_tf32_k(
    const float* __restrict__ A, const float* __restrict__ B,
    float* __restrict__ C, int M, int N, int K) {
    __shared__ float As[128][36];   // stride 36 == 4 (mod 32): conflict-free frag loads
    __shared__ float Bs[32][136];   // stride 136 == 8 (mod 32)

    const int bm = blockIdx.y * 128, bn = blockIdx.x * 128;
    const int tid = threadIdx.x, warp = tid >> 5, lane = tid & 31;
    const int wm = (warp >> 2) * 64, wn = (warp & 3) * 32;
    const int g = lane >> 2, t = lane & 3;

    float acc[4][4][4];
#pragma unroll
    for (int mt = 0; mt < 4; mt++)
#pragma unroll
        for (int nt = 0; nt < 4; nt++)
#pragma unroll
            for (int i = 0; i < 4; i++) acc[mt][nt][i] = 0.f;

    for (int k0 = 0; k0 < K; k0 += 32) {
#pragma unroll
        for (int i = 0; i < 4; i++) {
            int idx = tid + i * 256;
            // A tile: 128 rows x 32 cols = 1024 float4
            int ra = idx >> 3, ca = (idx & 7) << 2;
            float4 va = *(const float4*)(A + (size_t)(bm + ra) * K + k0 + ca);
            float4 ta = {f2tf(va.x), f2tf(va.y), f2tf(va.z), f2tf(va.w)};
            *(float4*)&As[ra][ca] = ta;
            // B tile: 32 rows x 128 cols = 1024 float4
            int rb = idx >> 5, cb = (idx & 31) << 2;
            float4 vb = *(const float4*)(B + (size_t)(k0 + rb) * N + bn + cb);
            float4 tb = {f2tf(vb.x), f2tf(vb.y), f2tf(vb.z), f2tf(vb.w)};
            *(float4*)&Bs[rb][cb] = tb;
        }
        __syncthreads();

#pragma unroll
        for (int kk = 0; kk < 32; kk += 8) {
            unsigned a[4][4], b[4][2];
#pragma unroll
            for (int mt = 0; mt < 4; mt++) {
                int r0 = wm + mt * 16 + g;
                a[mt][0] = __float_as_uint(As[r0][kk + t]);
                a[mt][1] = __float_as_uint(As[r0 + 8][kk + t]);
                a[mt][2] = __float_as_uint(As[r0][kk + t + 4]);
                a[mt][3] = __float_as_uint(As[r0 + 8][kk + t + 4]);
            }
#pragma unroll
            for (int nt = 0; nt < 4; nt++) {
                b[nt][0] = __float_as_uint(Bs[kk + t][wn + nt * 8 + g]);
                b[nt][1] = __float_as_uint(Bs[kk + t + 4][wn + nt * 8 + g]);
            }
#pragma unroll
            for (int mt = 0; mt < 4; mt++)
#pragma unroll
                for (int nt = 0; nt < 4; nt++) mma_tf32(acc[mt][nt], a[mt], b[nt]);
        }
        __syncthreads();
    }

#pragma unroll
    for (int mt = 0; mt < 4; mt++)
#pragma unroll
        for (int nt = 0; nt < 4; nt++) {
            int r0 = bm + wm + mt * 16 + g;
            int c0 = bn + wn + nt * 8 + 2 * t;
            float2 v0 = {acc[mt][nt][0], acc[mt][nt][1]};
            float2 v1 = {acc[mt][nt][2], acc[mt][nt][3]};
            *(float2*)&C[(size_t)r0 * N + c0] = v0;
            *(float2*)&C[(size_t)(r0 + 8) * N + c0] = v1;
        }
}

// ---------------------------------------------------------------------------
// RoPE (NeoX style, half=64), in-place on [B*S, nh, 128]
// ---------------------------------------------------------------------------
__global__ void rope_k(float* __restrict__ x, const int* __restrict__ pos,
                       int nh, int total) {
    int i = blockIdx.x * blockDim.x + threadIdx.x;
    if (i >= total) return;
    int j = i & 63;
    int h = (i >> 6) % nh;
    int row = i / (64 * nh);   // b*S + s
    float p = (float)pos[row];
    // inv_freq = 10000^(-j/64) = 2^(-j*log2(10000)/64)
    float fr = p * exp2f(-(float)j * 0.20762050593046062f);
    float sn, cs;
    sincosf(fr, &sn, &cs);
    float* ptr = x + ((size_t)row * nh + h) * 128 + j;
    float v1 = ptr[0], v2 = ptr[64];
    ptr[0] = v1 * cs - v2 * sn;
    ptr[64] = v2 * cs + v1 * sn;
}

// ---------------------------------------------------------------------------
// Flash attention, causal + key mask, GQA (4 q-heads per kv-head).
// Grid: (S/64 q-tiles, B*H). Block: 128 threads (4 warps, 16 q-rows each).
// Q tile 64x128 (scaled, tf32), K tile 32x128, V transposed in smem.
// ---------------------------------------------------------------------------
#define FLASH_SMEM_FLOATS (64*132 + 32*132 + 128*36 + 64*36)
#define FLASH_SMEM_BYTES  (FLASH_SMEM_FLOATS*4 + 32*4)

__global__ __launch_bounds__(128) void flash_k(
    const float* __restrict__ q, const float* __restrict__ k,
    const float* __restrict__ v, const int* __restrict__ am,
    float* __restrict__ ctx) {
    extern __shared__ float sm[];
    float (*Qs)[132] = (float (*)[132])sm;
    float (*Ks)[132] = (float (*)[132])(sm + 64 * 132);
    float (*Vt)[36]  = (float (*)[36])(sm + 64 * 132 + 32 * 132);
    float (*Ps)[36]  = (float (*)[36])(sm + 64 * 132 + 32 * 132 + 128 * 36);
    int* km = (int*)(sm + FLASH_SMEM_FLOATS);

    const int bh = blockIdx.y;
    const int b = bh >> 5, h = bh & 31, hk = h >> 2;
    const int q0 = blockIdx.x * 64;
    const int tid = threadIdx.x, warp = tid >> 5, lane = tid & 31;
    const int g = lane >> 2, t = lane & 3;
    const float scale = 0.08838834764831845f;  // 1/sqrt(128)

    // Load & scale Q tile (64x128)
#pragma unroll
    for (int i = 0; i < 16; i++) {
        int idx = tid + i * 128;
        int r = idx >> 5, c = (idx & 31) << 2;
        float4 vv = *(const float4*)(q + ((size_t)(b * Ss + q0 + r) * Hh + h) * HDd + c);
        float4 tv = {f2tf(vv.x * scale), f2tf(vv.y * scale),
                     f2tf(vv.z * scale), f2tf(vv.w * scale)};
        *(float4*)&Qs[r][c] = tv;
    }

    float o[16][4];
#pragma unroll
    for (int nt = 0; nt < 16; nt++)
#pragma unroll
        for (int i = 0; i < 4; i++) o[nt][i] = 0.f;
    float mrow0 = -1e30f, mrow1 = -1e30f, lrow0 = 0.f, lrow1 = 0.f;

    const int nkt = q0 / 32 + 2;
    const int qrow0 = q0 + warp * 16 + g, qrow1 = qrow0 + 8;

    for (int kt = 0; kt < nkt; kt++) {
        __syncthreads();
        // Load K tile (32x128) and V tile (transposed into Vt[128][32])
#pragma unroll
        for (int i = 0; i < 8; i++) {
            int idx = tid + i * 128;
            int r = idx >> 5, c = (idx & 31) << 2;
            size_t base = ((size_t)(b * Ss + kt * 32 + r) * HKVn + hk) * HDd + c;
            float4 kv = *(const float4*)(k + base);
            float4 tk = {f2tf(kv.x), f2tf(kv.y), f2tf(kv.z), f2tf(kv.w)};
            *(float4*)&Ks[r][c] = tk;
            float4 vv = *(const float4*)(v + base);
            Vt[c + 0][r] = f2tf(vv.x);
            Vt[c + 1][r] = f2tf(vv.y);
            Vt[c + 2][r] = f2tf(vv.z);
            Vt[c + 3][r] = f2tf(vv.w);
        }
        if (tid < 32) km[tid] = am[b * Ss + kt * 32 + tid];
        __syncthreads();

        // S = Q K^T (scaled): per warp 16 rows x 32 keys
        float s[4][4];
#pragma unroll
        for (int nt = 0; nt < 4; nt++)
#pragma unroll
            for (int i = 0; i < 4; i++) s[nt][i] = 0.f;
#pragma unroll
        for (int d8 = 0; d8 < 128; d8 += 8) {
            unsigned a[4];
            int r0 = warp * 16 + g;
            a[0] = __float_as_uint(Qs[r0][d8 + t]);
            a[1] = __float_as_uint(Qs[r0 + 8][d8 + t]);
            a[2] = __float_as_uint(Qs[r0][d8 + t + 4]);
            a[3] = __float_as_uint(Qs[r0 + 8][d8 + t + 4]);
#pragma unroll
            for (int nt = 0; nt < 4; nt++) {
                unsigned bb[2];
                bb[0] = __float_as_uint(Ks[nt * 8 + g][d8 + t]);
                bb[1] = __float_as_uint(Ks[nt * 8 + g][d8 + t + 4]);
                mma_tf32(s[nt], a, bb);
            }
        }

        // Causal + key mask, then online softmax
        float mx0 = -1e30f, mx1 = -1e30f;
#pragma unroll
        for (int nt = 0; nt < 4; nt++) {
            int cl = nt * 8 + 2 * t;              // local key col
            int c0 = kt * 32 + cl;                // global key col
            int m0 = km[cl], m1 = km[cl + 1];
            if (c0 > qrow0 || m0 == 0) s[nt][0] = -1e30f;
            if (c0 + 1 > qrow0 || m1 == 0) s[nt][1] = -1e30f;
            if (c0 > qrow1 || m0 == 0) s[nt][2] = -1e30f;
            if (c0 + 1 > qrow1 || m1 == 0) s[nt][3] = -1e30f;
            mx0 = fmaxf(mx0, fmaxf(s[nt][0], s[nt][1]));
            mx1 = fmaxf(mx1, fmaxf(s[nt][2], s[nt][3]));
        }
        mx0 = fmaxf(mx0, __shfl_xor_sync(0xffffffffu, mx0, 1));
        mx0 = fmaxf(mx0, __shfl_xor_sync(0xffffffffu, mx0, 2));
        mx1 = fmaxf(mx1, __shfl_xor_sync(0xffffffffu, mx1, 1));
        mx1 = fmaxf(mx1, __shfl_xor_sync(0xffffffffu, mx1, 2));

        float nm0 = fmaxf(mrow0, mx0), nm1 = fmaxf(mrow1, mx1);
        float al0 = __expf(mrow0 - nm0), al1 = __expf(mrow1 - nm1);
        mrow0 = nm0; mrow1 = nm1;

        float sum0 = 0.f, sum1 = 0.f;
#pragma unroll
        for (int nt = 0; nt < 4; nt++) {
            s[nt][0] = __expf(s[nt][0] - nm0);
            s[nt][1] = __expf(s[nt][1] - nm0);
            s[nt][2] = __expf(s[nt][2] - nm1);
            s[nt][3] = __expf(s[nt][3] - nm1);
            sum0 += s[nt][0] + s[nt][1];
            sum1 += s[nt][2] + s[nt][3];
        }
        sum0 += __shfl_xor_sync(0xffffffffu, sum0, 1);
        sum0 += __shfl_xor_sync(0xffffffffu, sum0, 2);
        sum1 += __shfl_xor_sync(0xffffffffu, sum1, 1);
        sum1 += __shfl_xor_sync(0xffffffffu, sum1, 2);
        lrow0 = lrow0 * al0 + sum0;
        lrow1 = lrow1 * al1 + sum1;

        // Rescale O accumulators
#pragma unroll
        for (int nt = 0; nt < 16; nt++) {
            o[nt][0] *= al0; o[nt][1] *= al0;
            o[nt][2] *= al1; o[nt][3] *= al1;
        }

        // Stage P (tf32) to smem for second MMA (warp-private region)
        __syncwarp();
        {
            int r0 = warp * 16 + g;
#pragma unroll
            for (int nt = 0; nt < 4; nt++) {
                float2 p0 = {f2tf(s[nt][0]), f2tf(s[nt][1])};
                float2 p1 = {f2tf(s[nt][2]), f2tf(s[nt][3])};
                *(float2*)&Ps[r0][nt * 8 + 2 * t] = p0;
                *(float2*)&Ps[r0 + 8][nt * 8 + 2 * t] = p1;
            }
        }
        __syncwarp();

        // O += P @ V
#pragma unroll
        for (int kk = 0; kk < 32; kk += 8) {
            unsigned a[4];
            int r0 = warp * 16 + g;
            a[0] = __float_as_uint(Ps[r0][kk + t]);
            a[1] = __float_as_uint(Ps[r0 + 8][kk + t]);
            a[2] = __float_as_uint(Ps[r0][kk + t + 4]);
            a[3] = __float_as_uint(Ps[r0 + 8][kk + t + 4]);
#pragma unroll
            for (int nt = 0; nt < 16; nt++) {
                unsigned bb[2];
                bb[0] = __float_as_uint(Vt[nt * 8 + g][kk + t]);
                bb[1] = __float_as_uint(Vt[nt * 8 + g][kk + t + 4]);
                mma_tf32(o[nt], a, bb);
            }
        }
    }

    // Finalize and write ctx [B*S, H*HD]
    float il0 = 1.f / lrow0, il1 = 1.f / lrow1;
    int r0 = q0 + warp * 16 + g;
#pragma unroll
    for (int nt = 0; nt < 16; nt++) {
        int c = h * 128 + nt * 8 + 2 * t;
        float2 v0 = {o[nt][0] * il0, o[nt][1] * il0};
        float2 v1 = {o[nt][2] * il1, o[nt][3] * il1};
        *(float2*)&ctx[(size_t)(b * Ss + r0) * Dd + c] = v0;
        *(float2*)&ctx[(size_t)(b * Ss + r0 + 8) * Dd + c] = v1;
    }
}

// ---------------------------------------------------------------------------
extern "C" void kernel_launch(void* const* d_in, const int* in_sizes, int n_in,
                              void* d_out, int out_size) {
    const float* hs = (const float*)d_in[0];
    const int* pos = (const int*)d_in[1];
    const int* am = (const int*)d_in[2];
    const float* Wq = (const float*)d_in[3];
    const float* Wk = (const float*)d_in[4];
    const float* Wv = (const float*)d_in[5];
    const float* Wo = (const float*)d_in[6];
    float* out = (float*)d_out;

    float *q, *k, *v, *ctx;
    cudaGetSymbolAddress((void**)&q, g_q);
    cudaGetSymbolAddress((void**)&k, g_k);
    cudaGetSymbolAddress((void**)&v, g_v);
    cudaGetSymbolAddress((void**)&ctx, g_ctx);

    cudaFuncSetAttribute(flash_k, cudaFuncAttributeMaxDynamicSharedMemorySize,
                         FLASH_SMEM_BYTES);

    // QKV projections
    gemm_tf32_k<<<dim3(Dd / 128, Mm / 128), 256>>>(hs, Wq, q, Mm, Dd, Dd);
    gemm_tf32_k<<<dim3((HKVn * HDd) / 128, Mm / 128), 256>>>(hs, Wk, k, Mm, HKVn * HDd, Dd);
    gemm_tf32_k<<<dim3((HKVn * HDd) / 128, Mm / 128), 256>>>(hs, Wv, v, Mm, HKVn * HDd, Dd);

    // RoPE on q and k
    int nq = Mm * Hh * 64;
    int nk = Mm * HKVn * 64;
    rope_k<<<(nq + 255) / 256, 256>>>(q, pos, Hh, nq);
    rope_k<<<(nk + 255) / 256, 256>>>(k, pos, HKVn, nk);

    // Attention
    flash_k<<<dim3(Ss / 64, Bb * Hh), 128, FLASH_SMEM_BYTES>>>(q, k, v, am, ctx);

    // Output projection
    gemm_tf32_k<<<dim3(Dd / 128, Mm / 128), 256>>>(ctx, Wo, out, Mm, Dd, Dd);
}